// round 1
// baseline (speedup 1.0000x reference)
#include <cuda_runtime.h>
#include <cstdint>

#define IN_CH   256
#define OUT_CH  256
#define HID     128
#define S_MAX   16384
#define N_MAX   1100000

// ---------------- scratch (device globals: no allocation allowed) ----------
__device__ float        g_gate[N_MAX];
__device__ float        g_e[N_MAX];
__device__ unsigned int g_segmax_u[S_MAX];
__device__ float        g_segmax[S_MAX];
__device__ float        g_segsum[S_MAX];
__device__ int          g_idx64;

// ---------------- helpers ---------------------------------------------------
__device__ __forceinline__ unsigned fenc(float f) {
    unsigned b = __float_as_uint(f);
    return (b & 0x80000000u) ? ~b : (b | 0x80000000u);
}
__device__ __forceinline__ float fdec(unsigned u) {
    return (u & 0x80000000u) ? __uint_as_float(u ^ 0x80000000u)
                             : __uint_as_float(~u);
}
__device__ __forceinline__ int load_idx(const void* idx, int i) {
    if (g_idx64) return (int)((const long long*)idx)[i];
    return ((const int*)idx)[i];
}

// ---------------- kernel 0: detect index dtype (int32 vs int64) ------------
// If the buffer is int64, values read as int64 near the middle are < 2^31
// (sorted uniform in [0,16384)). If it is int32, an int64 read there combines
// two nonzero ~8192 values -> >= 2^32. Reads stay within the first n*4 bytes.
__global__ void detect_idx_kernel(const void* __restrict__ idx, int n) {
    if (threadIdx.x == 0 && blockIdx.x == 0) {
        const long long* p = (const long long*)idx;
        int base = n / 4;
        int ok64 = 1;
        for (int i = 0; i < 8; i++) {
            long long v = p[base + i];
            if (v < 0 || v >= (1LL << 31)) ok64 = 0;
        }
        g_idx64 = ok64;
    }
}

// ---------------- kernel 1: init segment scratch ----------------------------
__global__ void init_seg_kernel() {
    int s = blockIdx.x * blockDim.x + threadIdx.x;
    if (s < S_MAX) {
        g_segmax_u[s] = 0u;   // encodes "less than any float"
        g_segsum[s]   = 0.f;
    }
}

// ---------------- kernel 2: gate GEMM (64x128 tile, K=256) -----------------
// h = relu(X @ W1 + b1); gate = h @ W2 + b2; fused segment-max atomic.
__global__ __launch_bounds__(256) void gate_kernel(
    const float* __restrict__ X, const void* __restrict__ idx,
    const float* __restrict__ W1, const float* __restrict__ b1,
    const float* __restrict__ W2, const float* __restrict__ b2, int n)
{
    __shared__ float As[16][68];
    __shared__ float Bs[16][128];
    __shared__ float red[64][17];

    const int tid = threadIdx.x;
    const int tx  = tid & 15;      // col group (8 cols each)
    const int ty  = tid >> 4;      // row group (4 rows each)
    const int rowBase = blockIdx.x * 64;

    float acc[4][8];
#pragma unroll
    for (int i = 0; i < 4; i++)
#pragma unroll
        for (int j = 0; j < 8; j++) acc[i][j] = 0.f;

    const int lm  = tid & 63;   // A-load: row in tile
    const int lk4 = tid >> 6;   // A-load: k-quad (0..3)

    for (int kt = 0; kt < 16; kt++) {
        // A tile: 64 rows x 16 k (transposed store)
        {
            int gr = rowBase + lm;
            float4 v = make_float4(0.f, 0.f, 0.f, 0.f);
            if (gr < n)
                v = *(const float4*)(X + (size_t)gr * IN_CH + kt * 16 + lk4 * 4);
            As[lk4 * 4 + 0][lm] = v.x;
            As[lk4 * 4 + 1][lm] = v.y;
            As[lk4 * 4 + 2][lm] = v.z;
            As[lk4 * 4 + 3][lm] = v.w;
        }
        // B tile: 16 k x 128 hid  (512 float4, 2 per thread)
        {
#pragma unroll
            for (int u = 0; u < 2; u++) {
                int f  = tid * 2 + u;
                int kk = f >> 5;       // 32 quads per k-row
                int nq = f & 31;
                *(float4*)&Bs[kk][nq * 4] =
                    *(const float4*)(W1 + (size_t)(kt * 16 + kk) * HID + nq * 4);
            }
        }
        __syncthreads();
#pragma unroll
        for (int kk = 0; kk < 16; kk++) {
            float4 a  = *(float4*)&As[kk][ty * 4];
            float4 b0 = *(float4*)&Bs[kk][tx * 8];
            float4 b1v = *(float4*)&Bs[kk][tx * 8 + 4];
            float am[4] = {a.x, a.y, a.z, a.w};
            float bn[8] = {b0.x, b0.y, b0.z, b0.w, b1v.x, b1v.y, b1v.z, b1v.w};
#pragma unroll
            for (int i = 0; i < 4; i++)
#pragma unroll
                for (int j = 0; j < 8; j++) acc[i][j] = fmaf(am[i], bn[j], acc[i][j]);
        }
        __syncthreads();
    }

    // epilogue: relu(+b1), dot with W2 over this thread's 8 cols
    float part[4];
#pragma unroll
    for (int i = 0; i < 4; i++) {
        float s = 0.f;
#pragma unroll
        for (int j = 0; j < 8; j++) {
            float h = fmaxf(acc[i][j] + b1[tx * 8 + j], 0.f);
            s = fmaf(h, W2[tx * 8 + j], s);
        }
        part[i] = s;
    }
#pragma unroll
    for (int i = 0; i < 4; i++) red[ty * 4 + i][tx] = part[i];
    __syncthreads();

    if (tid < 64) {
        float g = b2[0];
#pragma unroll
        for (int t = 0; t < 16; t++) g += red[tid][t];
        int gr = rowBase + tid;
        if (gr < n) {
            g_gate[gr] = g;
            int s = load_idx(idx, gr);
            atomicMax(&g_segmax_u[s], fenc(g));
        }
    }
}

// ---------------- kernel 3: decode segment max ------------------------------
__global__ void seg_decode_kernel() {
    int s = blockIdx.x * blockDim.x + threadIdx.x;
    if (s < S_MAX) {
        unsigned u = g_segmax_u[s];
        g_segmax[s] = (u == 0u) ? 0.f : fdec(u);   // empty segment -> 0 (matches ref)
    }
}

// ---------------- kernel 4: e = exp(gate - segmax); segment-sum -------------
__global__ void esum_kernel(const void* __restrict__ idx, int n) {
    int i = blockIdx.x * blockDim.x + threadIdx.x;
    if (i < n) {
        int s   = load_idx(idx, i);
        float e = expf(g_gate[i] - g_segmax[s]);
        g_e[i]  = e;
        atomicAdd(&g_segsum[s], e);
    }
}

// ---------------- kernel 5: transform GEMM + alpha-weighted segmented scatter
// Tile: 64 rows x 256 cols, K=256 (BK=16). 256 threads, each 4x16 accum.
// Epilogue: t=relu(acc+bt)*alpha staged into smem, then per-column segmented
// reduction over the 64 sorted rows; one atomicAdd per (segment,col) per tile.
__global__ __launch_bounds__(256) void transform_kernel(
    const float* __restrict__ X, const void* __restrict__ idx,
    const float* __restrict__ Wt, const float* __restrict__ bt,
    float* __restrict__ out, int n)
{
    extern __shared__ float sm[];
    float* As = sm;                  // [16][68]  = 1088 floats
    float* Bs = sm + 16 * 68;        // [16][256] = 4096 floats
    __shared__ int   sidx[64];
    __shared__ float salpha[64];

    const int tid = threadIdx.x;
    const int tx  = tid & 15;       // col group (16 cols)
    const int ty  = tid >> 4;       // row group (4 rows)
    const int rowBase = blockIdx.x * 64;

    float acc[4][16];
#pragma unroll
    for (int i = 0; i < 4; i++)
#pragma unroll
        for (int j = 0; j < 16; j++) acc[i][j] = 0.f;

    const int lm  = tid & 63;
    const int lk4 = tid >> 6;

    for (int kt = 0; kt < 16; kt++) {
        {
            int gr = rowBase + lm;
            float4 v = make_float4(0.f, 0.f, 0.f, 0.f);
            if (gr < n)
                v = *(const float4*)(X + (size_t)gr * IN_CH + kt * 16 + lk4 * 4);
            As[(lk4 * 4 + 0) * 68 + lm] = v.x;
            As[(lk4 * 4 + 1) * 68 + lm] = v.y;
            As[(lk4 * 4 + 2) * 68 + lm] = v.z;
            As[(lk4 * 4 + 3) * 68 + lm] = v.w;
        }
        {
#pragma unroll
            for (int u = 0; u < 4; u++) {
                int f  = tid * 4 + u;
                int kk = f >> 6;      // 64 quads per k-row
                int nq = f & 63;
                *(float4*)&Bs[kk * 256 + nq * 4] =
                    *(const float4*)(Wt + (size_t)(kt * 16 + kk) * OUT_CH + nq * 4);
            }
        }
        __syncthreads();
#pragma unroll
        for (int kk = 0; kk < 16; kk++) {
            float4 a = *(float4*)&As[kk * 68 + ty * 4];
            float am[4] = {a.x, a.y, a.z, a.w};
            float bn[16];
#pragma unroll
            for (int q = 0; q < 4; q++) {
                float4 b = *(float4*)&Bs[kk * 256 + tx * 16 + q * 4];
                bn[q * 4 + 0] = b.x; bn[q * 4 + 1] = b.y;
                bn[q * 4 + 2] = b.z; bn[q * 4 + 3] = b.w;
            }
#pragma unroll
            for (int i = 0; i < 4; i++)
#pragma unroll
                for (int j = 0; j < 16; j++) acc[i][j] = fmaf(am[i], bn[j], acc[i][j]);
        }
        __syncthreads();
    }

    const int limit = min(64, n - rowBase);
    if (tid < 64) {
        if (tid < limit) {
            int s = load_idx(idx, rowBase + tid);
            sidx[tid] = s;
            float denom = fmaxf(g_segsum[s], 1e-16f);
            salpha[tid] = g_e[rowBase + tid] / denom;
        } else {
            sidx[tid]   = -1;
            salpha[tid] = 0.f;
        }
    }
    __syncthreads();   // everyone done with As/Bs; smem reused below

    // stage weighted tile: Ts[64][257]
    float* Ts = sm;
#pragma unroll
    for (int i = 0; i < 4; i++) {
        float al = salpha[ty * 4 + i];
#pragma unroll
        for (int j = 0; j < 16; j++) {
            int c  = tx * 16 + j;
            float t = fmaxf(acc[i][j] + bt[c], 0.f);
            Ts[(ty * 4 + i) * 257 + c] = t * al;
        }
    }
    __syncthreads();

    // per-column segmented reduction over sorted rows
    if (limit > 0) {
        const int c = tid;                 // 256 columns
        float a  = 0.f;
        int prev = sidx[0];
        for (int r = 0; r < limit; r++) {
            int s = sidx[r];
            if (s != prev) {
                atomicAdd(&out[(size_t)prev * OUT_CH + c], a);
                a = 0.f;
                prev = s;
            }
            a += Ts[r * 257 + c];
        }
        atomicAdd(&out[(size_t)prev * OUT_CH + c], a);
    }
}

// ---------------- launch -----------------------------------------------------
extern "C" void kernel_launch(void* const* d_in, const int* in_sizes, int n_in,
                              void* d_out, int out_size)
{
    const float* X   = (const float*)d_in[0];
    const void*  idx = d_in[1];
    // dim_size may or may not be passed as an input scalar; detect by size.
    int base = (n_in >= 9 && in_sizes[2] <= 16) ? 3 : 2;
    const float* W1 = (const float*)d_in[base + 0];
    const float* b1 = (const float*)d_in[base + 1];
    const float* W2 = (const float*)d_in[base + 2];
    const float* b2 = (const float*)d_in[base + 3];
    const float* Wt = (const float*)d_in[base + 4];
    const float* bt = (const float*)d_in[base + 5];

    const int n = in_sizes[0] / IN_CH;
    float* out = (float*)d_out;

    // transform kernel needs 64*257*4 = 65792 B dynamic smem (> 48K default)
    const int TR_SMEM = 64 * 257 * 4;
    cudaFuncSetAttribute(transform_kernel,
                         cudaFuncAttributeMaxDynamicSharedMemorySize, TR_SMEM);

    cudaMemsetAsync(d_out, 0, (size_t)out_size * sizeof(float), 0);
    detect_idx_kernel<<<1, 32>>>(idx, n);
    init_seg_kernel<<<(S_MAX + 255) / 256, 256>>>();

    const int nTiles = (n + 63) / 64;
    gate_kernel<<<nTiles, 256>>>(X, idx, W1, b1, W2, b2, n);
    seg_decode_kernel<<<(S_MAX + 255) / 256, 256>>>();
    esum_kernel<<<(n + 255) / 256, 256>>>(idx, n);
    transform_kernel<<<nTiles, 256, TR_SMEM>>>(X, idx, Wt, bt, out, n);
}

// round 2
// speedup vs baseline: 6.7764x; 6.7764x over previous
#include <cuda_runtime.h>
#include <cuda_bf16.h>
#include <cstdint>

#define IN_CH   256
#define OUT_CH  256
#define HID     128
#define S_MAX   16384
#define N_MAX   1100000

// smem geometry (bf16 element units)
#define SA      40            // A tile stride (32 k + 8 pad) -> conflict-free LDSM
#define SB      136           // B tile stride (128 n + 8 pad)
#define TSST    133           // epilogue fp32 staging stride
#define AHI_OFF 0
#define ALO_OFF 5120          // 128*40
#define BHI_OFF 10240
#define BLO_OFF 14592         // +32*136
#define BUF_ELEMS 18944       // bf16 per pipeline buffer
#define SMEM_BYTES 75776      // 2 buffers * 18944 * 2B

// ---------------- scratch (device globals: no allocation allowed) ----------
__device__ float          g_gate[N_MAX];
__device__ float          g_e[N_MAX];
__device__ unsigned int   g_segmax_u[S_MAX];
__device__ float          g_segmax[S_MAX];
__device__ float          g_segsum[S_MAX];
__device__ int            g_idx64;
__device__ __nv_bfloat16  g_W1hi[IN_CH * HID];
__device__ __nv_bfloat16  g_W1lo[IN_CH * HID];
__device__ __nv_bfloat16  g_Wthi[IN_CH * OUT_CH];
__device__ __nv_bfloat16  g_Wtlo[IN_CH * OUT_CH];

// ---------------- helpers ---------------------------------------------------
__device__ __forceinline__ unsigned fenc(float f) {
    unsigned b = __float_as_uint(f);
    return (b & 0x80000000u) ? ~b : (b | 0x80000000u);
}
__device__ __forceinline__ float fdec(unsigned u) {
    return (u & 0x80000000u) ? __uint_as_float(u ^ 0x80000000u)
                             : __uint_as_float(~u);
}
__device__ __forceinline__ int load_idx(const void* idx, int i) {
    if (g_idx64) return (int)((const long long*)idx)[i];
    return ((const int*)idx)[i];
}

#define LDSM4(R, ADDR)                                                        \
    asm volatile("ldmatrix.sync.aligned.m8n8.x4.shared.b16 {%0,%1,%2,%3},[%4];" \
                 : "=r"(R[0]), "=r"(R[1]), "=r"(R[2]), "=r"(R[3]) : "r"(ADDR))
#define LDSM4T(R, ADDR)                                                       \
    asm volatile("ldmatrix.sync.aligned.m8n8.x4.trans.shared.b16 {%0,%1,%2,%3},[%4];" \
                 : "=r"(R[0]), "=r"(R[1]), "=r"(R[2]), "=r"(R[3]) : "r"(ADDR))
#define MMA_BF16(C, A, B0, B1)                                                \
    asm volatile("mma.sync.aligned.m16n8k16.row.col.f32.bf16.bf16.f32 "       \
                 "{%0,%1,%2,%3},{%4,%5,%6,%7},{%8,%9},{%0,%1,%2,%3};"         \
                 : "+f"(C[0]), "+f"(C[1]), "+f"(C[2]), "+f"(C[3])             \
                 : "r"(A[0]), "r"(A[1]), "r"(A[2]), "r"(A[3]),                \
                   "r"(B0), "r"(B1))

// ---------------- tiny kernels ----------------------------------------------
__global__ void detect_idx_kernel(const void* __restrict__ idx, int n) {
    if (threadIdx.x == 0 && blockIdx.x == 0) {
        const long long* p = (const long long*)idx;
        int base = n / 4;
        int ok64 = 1;
        for (int i = 0; i < 8; i++) {
            long long v = p[base + i];
            if (v < 0 || v >= (1LL << 31)) ok64 = 0;
        }
        g_idx64 = ok64;
    }
}

__global__ void init_seg_kernel() {
    int s = blockIdx.x * blockDim.x + threadIdx.x;
    if (s < S_MAX) {
        g_segmax_u[s] = 0u;
        g_segsum[s]   = 0.f;
    }
}

__global__ void convert_w_kernel(const float* __restrict__ W1,
                                 const float* __restrict__ Wt) {
    int i = blockIdx.x * blockDim.x + threadIdx.x;
    if (i < IN_CH * OUT_CH) {
        float v = Wt[i];
        __nv_bfloat16 h = __float2bfloat16(v);
        g_Wthi[i] = h;
        g_Wtlo[i] = __float2bfloat16(v - __bfloat162float(h));
    }
    if (i < IN_CH * HID) {
        float v = W1[i];
        __nv_bfloat16 h = __float2bfloat16(v);
        g_W1hi[i] = h;
        g_W1lo[i] = __float2bfloat16(v - __bfloat162float(h));
    }
}

__global__ void seg_decode_kernel() {
    int s = blockIdx.x * blockDim.x + threadIdx.x;
    if (s < S_MAX) {
        unsigned u = g_segmax_u[s];
        g_segmax[s] = (u == 0u) ? 0.f : fdec(u);
    }
}

__global__ void esum_kernel(const void* __restrict__ idx, int n) {
    int i = blockIdx.x * blockDim.x + threadIdx.x;
    if (i < n) {
        int s   = load_idx(idx, i);
        float e = expf(g_gate[i] - g_segmax[s]);
        g_e[i]  = e;
        atomicAdd(&g_segsum[s], e);
    }
}

// ---------------- main GEMM kernel (split-bf16 mma.sync) --------------------
// GATE=1: C = X @ W1 [128 hid cols], epilogue relu(+b1)·W2 + b2 -> gate,
//         fused segment-max.
// GATE=0: C = X @ Wt tile [128 of 256 cols], epilogue relu(+bt)*alpha,
//         segmented column scan + atomicAdd scatter.
template <int GATE>
__global__ __launch_bounds__(256, 2) void mma_gemm_kernel(
    const float* __restrict__ X, const void* __restrict__ idx,
    const float* __restrict__ bias,                 // b1 or bt
    const float* __restrict__ W2, const float* __restrict__ b2,
    float* __restrict__ out, int n)
{
    extern __shared__ __nv_bfloat16 sm[];
    __shared__ int   sidx[128];
    __shared__ float srow[128];   // alpha (transform) / b1 (gate)
    __shared__ float sw2[128];    // W2 (gate only)

    const int tid  = threadIdx.x;
    const int lane = tid & 31;
    const int warp = tid >> 5;
    const int warpRow = (warp & 3) * 32;
    const int warpCol = (warp >> 2) * 64;
    const int rowBase = blockIdx.x * 128;
    const int nBase   = GATE ? 0 : (blockIdx.y * 128);
    const int ldB     = GATE ? HID : OUT_CH;
    const __nv_bfloat16* Bgh = GATE ? g_W1hi : g_Wthi;
    const __nv_bfloat16* Bgl = GATE ? g_W1lo : g_Wtlo;

    const uint32_t smemBase = (uint32_t)__cvta_generic_to_shared(sm);

    float acc[2][8][4];
#pragma unroll
    for (int mt = 0; mt < 2; mt++)
#pragma unroll
        for (int nt = 0; nt < 8; nt++)
#pragma unroll
            for (int q = 0; q < 4; q++) acc[mt][nt][q] = 0.f;

    float4 aPref[4];

    auto loadA = [&](int kt) {
#pragma unroll
        for (int u = 0; u < 4; u++) {
            int f = tid + 256 * u;
            int row = f >> 3, kq = f & 7;
            int gr = rowBase + row;
            aPref[u] = (gr < n)
                ? *(const float4*)(X + (size_t)gr * IN_CH + kt * 32 + kq * 4)
                : make_float4(0.f, 0.f, 0.f, 0.f);
        }
    };
    auto stsA = [&](int b) {
#pragma unroll
        for (int u = 0; u < 4; u++) {
            int f = tid + 256 * u;
            int row = f >> 3, kq = f & 7;
            float4 v = aPref[u];
            __nv_bfloat16 hx = __float2bfloat16(v.x);
            __nv_bfloat16 hy = __float2bfloat16(v.y);
            __nv_bfloat16 hz = __float2bfloat16(v.z);
            __nv_bfloat16 hw = __float2bfloat16(v.w);
            __nv_bfloat16 lx = __float2bfloat16(v.x - __bfloat162float(hx));
            __nv_bfloat16 ly = __float2bfloat16(v.y - __bfloat162float(hy));
            __nv_bfloat16 lz = __float2bfloat16(v.z - __bfloat162float(hz));
            __nv_bfloat16 lw = __float2bfloat16(v.w - __bfloat162float(hw));
            int off = b * BUF_ELEMS + AHI_OFF + row * SA + kq * 4;
            ((__nv_bfloat162*)&sm[off])[0] = __nv_bfloat162(hx, hy);
            ((__nv_bfloat162*)&sm[off])[1] = __nv_bfloat162(hz, hw);
            int offL = off + (ALO_OFF - AHI_OFF);
            ((__nv_bfloat162*)&sm[offL])[0] = __nv_bfloat162(lx, ly);
            ((__nv_bfloat162*)&sm[offL])[1] = __nv_bfloat162(lz, lw);
        }
    };
    auto cpB = [&](int b, int kt) {
#pragma unroll
        for (int u = 0; u < 2; u++) {
            int e = tid + 256 * u;
            int krow = e >> 4, c16 = e & 15;
            const __nv_bfloat16* srcH =
                Bgh + (size_t)(kt * 32 + krow) * ldB + nBase + c16 * 8;
            const __nv_bfloat16* srcL =
                Bgl + (size_t)(kt * 32 + krow) * ldB + nBase + c16 * 8;
            uint32_t dstH = smemBase +
                (uint32_t)(b * BUF_ELEMS + BHI_OFF + krow * SB + c16 * 8) * 2u;
            uint32_t dstL = dstH + (BLO_OFF - BHI_OFF) * 2u;
            asm volatile("cp.async.ca.shared.global [%0],[%1],16;\n"
                         :: "r"(dstH), "l"(__cvta_generic_to_global(srcH)));
            asm volatile("cp.async.ca.shared.global [%0],[%1],16;\n"
                         :: "r"(dstL), "l"(__cvta_generic_to_global(srcL)));
        }
    };
    auto compute = [&](int b) {
#pragma unroll
        for (int kk = 0; kk < 32; kk += 16) {
            uint32_t ah[2][4], al[2][4];
#pragma unroll
            for (int mt = 0; mt < 2; mt++) {
                int row = warpRow + mt * 16 + (lane & 15);
                int kof = kk + ((lane >> 4) << 3);
                uint32_t adH = smemBase +
                    (uint32_t)(b * BUF_ELEMS + AHI_OFF + row * SA + kof) * 2u;
                LDSM4(ah[mt], adH);
                uint32_t adL = adH + (ALO_OFF - AHI_OFF) * 2u;
                LDSM4(al[mt], adL);
            }
#pragma unroll
            for (int p = 0; p < 4; p++) {
                int krow = kk + (lane & 7) + (((lane >> 3) & 1) << 3);
                int ncol = warpCol + p * 16 + ((lane >> 4) << 3);
                uint32_t bH = smemBase +
                    (uint32_t)(b * BUF_ELEMS + BHI_OFF + krow * SB + ncol) * 2u;
                uint32_t bh[4], bl[4];
                LDSM4T(bh, bH);
                uint32_t bL = bH + (BLO_OFF - BHI_OFF) * 2u;
                LDSM4T(bl, bL);
#pragma unroll
                for (int mt = 0; mt < 2; mt++) {
                    MMA_BF16(acc[mt][2 * p],     ah[mt], bh[0], bh[1]);
                    MMA_BF16(acc[mt][2 * p],     ah[mt], bl[0], bl[1]);
                    MMA_BF16(acc[mt][2 * p],     al[mt], bh[0], bh[1]);
                    MMA_BF16(acc[mt][2 * p + 1], ah[mt], bh[2], bh[3]);
                    MMA_BF16(acc[mt][2 * p + 1], ah[mt], bl[2], bl[3]);
                    MMA_BF16(acc[mt][2 * p + 1], al[mt], bh[2], bh[3]);
                }
            }
        }
    };

    // ---- pipeline: 8 K-steps of 32 ----
    loadA(0);
    cpB(0, 0);
    asm volatile("cp.async.commit_group;");
    stsA(0);
    asm volatile("cp.async.wait_group 0;");
    __syncthreads();

#pragma unroll 1
    for (int kt = 0; kt < 8; kt++) {
        int cur = kt & 1;
        bool more = (kt < 7);
        if (more) {
            loadA(kt + 1);
            cpB(1 - cur, kt + 1);
            asm volatile("cp.async.commit_group;");
        }
        compute(cur);
        if (more) {
            stsA(1 - cur);
            asm volatile("cp.async.wait_group 0;");
        }
        __syncthreads();
    }

    // ---- epilogue: stage C tile into fp32 smem ----
    if (GATE) {
        if (tid < 128) {
            srow[tid] = bias[tid];  // b1
            sw2[tid]  = W2[tid];
        }
    } else {
        if (tid < 128) {
            int gr = rowBase + tid;
            if (gr < n) {
                int s = load_idx(idx, gr);
                sidx[tid] = s;
                srow[tid] = g_e[gr] / fmaxf(g_segsum[s], 1e-16f);  // alpha
            } else {
                sidx[tid] = -1;
                srow[tid] = 0.f;
            }
        }
    }

    float* Tsm = (float*)sm;
#pragma unroll
    for (int mt = 0; mt < 2; mt++)
#pragma unroll
        for (int nt = 0; nt < 8; nt++) {
            int r0 = warpRow + mt * 16 + (lane >> 2);
            int c0 = warpCol + nt * 8 + ((lane & 3) << 1);
            Tsm[r0 * TSST + c0]           = acc[mt][nt][0];
            Tsm[r0 * TSST + c0 + 1]       = acc[mt][nt][1];
            Tsm[(r0 + 8) * TSST + c0]     = acc[mt][nt][2];
            Tsm[(r0 + 8) * TSST + c0 + 1] = acc[mt][nt][3];
        }
    __syncthreads();

    if (GATE) {
        if (tid < 128) {
            int gr = rowBase + tid;
            if (gr < n) {
                float g = b2[0];
#pragma unroll 8
                for (int j = 0; j < HID; j++)
                    g = fmaf(fmaxf(Tsm[tid * TSST + j] + srow[j], 0.f), sw2[j], g);
                g_gate[gr] = g;
                int s = load_idx(idx, gr);
                atomicMax(&g_segmax_u[s], fenc(g));
            }
        }
    } else {
        // segmented column scan over sorted rows; two threads per column
        int c = tid & 127;
        int rStart = (tid >> 7) * 64;
        float btc = bias[nBase + c];
        float a = 0.f;
        int prev = -1;
        for (int r = rStart; r < rStart + 64; r++) {
            int s = sidx[r];
            if (s < 0) break;
            if (s != prev) {
                if (prev >= 0)
                    atomicAdd(&out[(size_t)prev * OUT_CH + nBase + c], a);
                a = 0.f;
                prev = s;
            }
            a = fmaf(fmaxf(Tsm[r * TSST + c] + btc, 0.f), srow[r], a);
        }
        if (prev >= 0)
            atomicAdd(&out[(size_t)prev * OUT_CH + nBase + c], a);
    }
}

// ---------------- launch -----------------------------------------------------
extern "C" void kernel_launch(void* const* d_in, const int* in_sizes, int n_in,
                              void* d_out, int out_size)
{
    const float* X   = (const float*)d_in[0];
    const void*  idx = d_in[1];
    int base = (n_in >= 9 && in_sizes[2] <= 16) ? 3 : 2;
    const float* W1 = (const float*)d_in[base + 0];
    const float* b1 = (const float*)d_in[base + 1];
    const float* W2 = (const float*)d_in[base + 2];
    const float* b2 = (const float*)d_in[base + 3];
    const float* Wt = (const float*)d_in[base + 4];
    const float* bt = (const float*)d_in[base + 5];

    const int n = in_sizes[0] / IN_CH;
    float* out = (float*)d_out;

    cudaFuncSetAttribute(mma_gemm_kernel<1>,
                         cudaFuncAttributeMaxDynamicSharedMemorySize, SMEM_BYTES);
    cudaFuncSetAttribute(mma_gemm_kernel<0>,
                         cudaFuncAttributeMaxDynamicSharedMemorySize, SMEM_BYTES);

    cudaMemsetAsync(d_out, 0, (size_t)out_size * sizeof(float), 0);
    detect_idx_kernel<<<1, 32>>>(idx, n);
    init_seg_kernel<<<(S_MAX + 255) / 256, 256>>>();
    convert_w_kernel<<<(IN_CH * OUT_CH + 255) / 256, 256>>>(W1, Wt);

    const int nTiles = (n + 127) / 128;
    mma_gemm_kernel<1><<<dim3(nTiles, 1), 256, SMEM_BYTES>>>(
        X, idx, b1, W2, b2, nullptr, n);
    seg_decode_kernel<<<(S_MAX + 255) / 256, 256>>>();
    esum_kernel<<<(n + 255) / 256, 256>>>(idx, n);
    mma_gemm_kernel<0><<<dim3(nTiles, 2), 256, SMEM_BYTES>>>(
        X, idx, bt, nullptr, nullptr, out, n);
}